// round 1
// baseline (speedup 1.0000x reference)
#include <cuda_runtime.h>
#include <cuda_bf16.h>

// ============================================================================
// CapLayerLP: 20-iteration predictor-corrector primal-dual interior point QP
//   min 0.5*eps*||x||^2 + p.x   s.t.  G x <= h
// with G = [1^T; -I; I; f^T; -f^T]  (n=1024, m=2n+3=2051).
//
// Key structural fact: the reduced KKT matrix
//   K = eps*I + diag(z1/s1 + z2/s2) + w0*(1 1^T) + (wA+wB)*(f f^T)
// is DIAGONAL + RANK-2, so each "Cholesky solve" becomes a Woodbury solve
// with a 2x2 capacitance matrix: pure O(n) vector work + block reductions.
// Entire solver runs in ONE block of 1024 threads (thread i owns coord i;
// thread 0 owns the 3 scalar constraints). fp64 throughout to track the
// fp64 reference trajectory.
// ============================================================================

#define NV    1024
#define MCON  2051.0      // 2*NV + 3
#define EPSR  1e-4
#define CCAP  10.0
#define NWARPS 32
#define ITERS 20

__device__ __forceinline__ double wrs(double v) {
#pragma unroll
    for (int o = 16; o > 0; o >>= 1) v += __shfl_down_sync(0xffffffffu, v, o);
    return v;
}
__device__ __forceinline__ double wrmax(double v) {
#pragma unroll
    for (int o = 16; o > 0; o >>= 1) v = fmax(v, __shfl_down_sync(0xffffffffu, v, o));
    return v;
}

// shared scalar slots
enum {
    SV_Z0 = 0, SV_ZA, SV_ZB,          // dual scalars (read by all threads)
    SV_T0, SV_TA, SV_TB,              // t-scalars for rhs (predictor/corrector reuse)
    SV_Y1, SV_Y2,                     // Woodbury 2x2 solution
    SV_AAFF, SV_SMU, SV_ALPHA,
    SV_S0, SV_SA, SV_SB,              // slack scalars (thread-0 state)
    SV_RP0, SV_RPA, SV_RPB,
    SV_IS0, SV_ISA, SV_ISB,
    SV_IZ0, SV_IZA, SV_IZB,
    SV_W0, SV_WA, SV_WB,
    SV_MU,
    SV_M11, SV_M22, SV_M12, SV_DETINV,
    SV_DS0A, SV_DSAA, SV_DSBA, SV_DZ0A, SV_DZAA, SV_DZBA,
    SV_RSZ0, SV_RSZA, SV_RSZB,
    SV_HA, SV_HB,
    SV_CNT
};

__global__ void __launch_bounds__(NV, 1)
pdip_kernel(const float* __restrict__ xin, const int* __restrict__ male,
            float* __restrict__ out)
{
    const int i    = threadIdx.x;
    const int lane = i & 31;
    const int wid  = i >> 5;

    __shared__ double wb[5][NWARPS];
    __shared__ double sv[SV_CNT];

    const double pi = -(double)xin[i];     // p = -x_input
    const double fi = (double)male[i];     // 0/1 fairness mask

    // ---- init: n_male reduction, h scalars, scalar state ----
    {
        double v = wrs(fi);
        if (lane == 0) wb[0][wid] = v;
    }
    __syncthreads();
    if (wid == 0) {
        double v = wrs(wb[0][lane]);
        if (lane == 0) {
            double r = CCAP * v / (double)NV;
            sv[SV_HA] = r + 1.0;
            sv[SV_HB] = -r;
            sv[SV_S0] = 1.0; sv[SV_Z0] = 1.0;
            sv[SV_SA] = 1.0; sv[SV_ZA] = 1.0;
            sv[SV_SB] = 1.0; sv[SV_ZB] = 1.0;
        }
    }
    __syncthreads();

    // per-coordinate state
    double xi = 0.0, s1 = 1.0, z1 = 1.0, s2 = 1.0, z2 = 1.0;

    for (int it = 0; it < ITERS; ++it) {
        const double z0 = sv[SV_Z0], zA = sv[SV_ZA], zB = sv[SV_ZB];

        // per-iteration reciprocals (the only elementwise fp64 divides)
        const double invs1 = 1.0 / s1, invs2 = 1.0 / s2;
        const double invz1 = 1.0 / z1, invz2 = 1.0 / z2;
        const double w1 = z1 * invs1, w2 = z2 * invs2;
        const double Dv = EPSR + w1 + w2;
        const double invD = 1.0 / Dv;
        const double rp1 = s1 - xi;                 // (-x)+s1-0
        const double rp2 = xi + s2 - 1.0;           // x+s2-1
        const double rx  = EPSR * xi + pi + (z0 - z1 + z2 + fi * (zA - zB));

        // ---- Pass 1: sum(x), f.x, s.z (vec), sum(1/D), sum(f/D) ----
        {
            double a0 = wrs(xi);
            double a1 = wrs(fi * xi);
            double a2 = wrs(s1 * z1 + s2 * z2);
            double a3 = wrs(invD);
            double a4 = wrs(fi * invD);
            if (lane == 0) { wb[0][wid]=a0; wb[1][wid]=a1; wb[2][wid]=a2; wb[3][wid]=a3; wb[4][wid]=a4; }
        }
        __syncthreads();
        if (wid == 0) {
            double sumx = wrs(wb[0][lane]);
            double fx   = wrs(wb[1][lane]);
            double szv  = wrs(wb[2][lane]);
            double SiD  = wrs(wb[3][lane]);
            double SfD  = wrs(wb[4][lane]);
            if (lane == 0) {
                double s0 = sv[SV_S0], sA = sv[SV_SA], sB = sv[SV_SB];
                double rp0 = sumx + s0 - CCAP;
                double rpA =  fx + sA - sv[SV_HA];
                double rpB = -fx + sB - sv[SV_HB];
                double mu  = (szv + s0*z0 + sA*zA + sB*zB) / MCON;
                double is0 = 1.0/s0, isA = 1.0/sA, isB = 1.0/sB;
                double iz0 = 1.0/z0, izA = 1.0/zA, izB = 1.0/zB;
                double w0 = z0*is0, wA = zA*isA, wB = zB*isB;
                double bW = wA + wB;
                sv[SV_RP0]=rp0; sv[SV_RPA]=rpA; sv[SV_RPB]=rpB; sv[SV_MU]=mu;
                sv[SV_IS0]=is0; sv[SV_ISA]=isA; sv[SV_ISB]=isB;
                sv[SV_IZ0]=iz0; sv[SV_IZA]=izA; sv[SV_IZB]=izB;
                sv[SV_W0]=w0;  sv[SV_WA]=wA;  sv[SV_WB]=wB;
                // predictor t-scalars (rsz_j = s_j z_j => t_j = w_j*rp_j - z_j)
                sv[SV_T0] = w0*rp0 - z0;
                sv[SV_TA] = wA*rpA - zA;
                sv[SV_TB] = wB*rpB - zB;
                // Woodbury capacitance M = C^-1 + U^T D^-1 U, C=diag(w0, bW)
                double M11 = 1.0/w0 + SiD;
                double M22 = 1.0/bW + SfD;
                sv[SV_M11]=M11; sv[SV_M22]=M22; sv[SV_M12]=SfD;
                sv[SV_DETINV] = 1.0 / (M11*M22 - SfD*SfD);
            }
        }
        __syncthreads();

        // ---- predictor rhs, g = D^-1 rhs ----
        double t1v = w1 * rp1 - z1;
        double t2v = w2 * rp2 - z2;
        double rhs = -(rx + sv[SV_T0] - t1v + t2v + fi * (sv[SV_TA] - sv[SV_TB]));
        double gi  = rhs * invD;

        // ---- Pass 2: u1 = sum(g), uf = sum(f g) ----
        {
            double a0 = wrs(gi), a1 = wrs(fi * gi);
            if (lane == 0) { wb[0][wid]=a0; wb[1][wid]=a1; }
        }
        __syncthreads();
        if (wid == 0) {
            double u1 = wrs(wb[0][lane]);
            double uf = wrs(wb[1][lane]);
            if (lane == 0) {
                double M11=sv[SV_M11], M22=sv[SV_M22], M12=sv[SV_M12], di=sv[SV_DETINV];
                sv[SV_Y1] = (M22*u1 - M12*uf) * di;
                sv[SV_Y2] = (M11*uf - M12*u1) * di;
            }
        }
        __syncthreads();

        // ---- affine direction ----
        double dxa  = gi - (sv[SV_Y1] + fi * sv[SV_Y2]) * invD;
        double ds1a = dxa - rp1;
        double ds2a = -rp2 - dxa;
        double dz1a = -z1 - w1 * ds1a;      // dz = -(s z + z ds)/s
        double dz2a = -z2 - w2 * ds2a;
        // fraction-to-boundary as max of (-dv)/v (division-free per component)
        double qs = fmax(fmax(-ds1a, 0.0) * invs1, fmax(-ds2a, 0.0) * invs2);
        double qz = fmax(fmax(-dz1a, 0.0) * invz1, fmax(-dz2a, 0.0) * invz2);

        // ---- Pass 3: sum(dx), f.dx, max qs, max qz ----
        {
            double a0 = wrs(dxa), a1 = wrs(fi * dxa);
            double a2 = wrmax(qs), a3 = wrmax(qz);
            if (lane == 0) { wb[0][wid]=a0; wb[1][wid]=a1; wb[2][wid]=a2; wb[3][wid]=a3; }
        }
        __syncthreads();
        if (wid == 0) {
            double sdx = wrs(wb[0][lane]);
            double fdx = wrs(wb[1][lane]);
            double mqs = wrmax(wb[2][lane]);
            double mqz = wrmax(wb[3][lane]);
            if (lane == 0) {
                double ds0 = -sv[SV_RP0] - sdx;
                double dsA = -sv[SV_RPA] - fdx;
                double dsB = -sv[SV_RPB] + fdx;
                double dz0 = -z0 - sv[SV_W0] * ds0;
                double dzA = -zA - sv[SV_WA] * dsA;
                double dzB = -zB - sv[SV_WB] * dsB;
                mqs = fmax(mqs, fmax(-ds0, 0.0) * sv[SV_IS0]);
                mqs = fmax(mqs, fmax(-dsA, 0.0) * sv[SV_ISA]);
                mqs = fmax(mqs, fmax(-dsB, 0.0) * sv[SV_ISB]);
                mqz = fmax(mqz, fmax(-dz0, 0.0) * sv[SV_IZ0]);
                mqz = fmax(mqz, fmax(-dzA, 0.0) * sv[SV_IZA]);
                mqz = fmax(mqz, fmax(-dzB, 0.0) * sv[SV_IZB]);
                double q = fmax(mqs, mqz);
                sv[SV_AAFF] = (q > 0.0) ? fmin(1.0, 1.0 / q) : 1.0;
                sv[SV_DS0A]=ds0; sv[SV_DSAA]=dsA; sv[SV_DSBA]=dsB;
                sv[SV_DZ0A]=dz0; sv[SV_DZAA]=dzA; sv[SV_DZBA]=dzB;
            }
        }
        __syncthreads();

        // ---- Pass 4: mu_aff, sigma, corrector t-scalars ----
        const double aaff = sv[SV_AAFF];
        {
            double m1 = (s1 + aaff*ds1a) * (z1 + aaff*dz1a)
                      + (s2 + aaff*ds2a) * (z2 + aaff*dz2a);
            double a0 = wrs(m1);
            if (lane == 0) wb[0][wid] = a0;
        }
        __syncthreads();
        if (wid == 0) {
            double mv = wrs(wb[0][lane]);
            if (lane == 0) {
                double s0 = sv[SV_S0], sA = sv[SV_SA], sB = sv[SV_SB];
                double ds0=sv[SV_DS0A], dsA=sv[SV_DSAA], dsB=sv[SV_DSBA];
                double dz0=sv[SV_DZ0A], dzA=sv[SV_DZAA], dzB=sv[SV_DZBA];
                double muaff = (mv
                    + (s0 + aaff*ds0) * (z0 + aaff*dz0)
                    + (sA + aaff*dsA) * (zA + aaff*dzA)
                    + (sB + aaff*dsB) * (zB + aaff*dzB)) / MCON;
                double mu = sv[SV_MU];
                double sg = muaff / mu;
                double smu = sg * sg * sg * mu;
                sv[SV_SMU] = smu;
                double rsz0 = s0*z0 + ds0*dz0 - smu;
                double rszA = sA*zA + dsA*dzA - smu;
                double rszB = sB*zB + dsB*dzB - smu;
                sv[SV_RSZ0]=rsz0; sv[SV_RSZA]=rszA; sv[SV_RSZB]=rszB;
                sv[SV_T0] = (z0*sv[SV_RP0] - rsz0) * sv[SV_IS0];
                sv[SV_TA] = (zA*sv[SV_RPA] - rszA) * sv[SV_ISA];
                sv[SV_TB] = (zB*sv[SV_RPB] - rszB) * sv[SV_ISB];
            }
        }
        __syncthreads();

        // ---- corrector rhs ----
        const double smu = sv[SV_SMU];
        double rsz1 = s1*z1 + ds1a*dz1a - smu;
        double rsz2 = s2*z2 + ds2a*dz2a - smu;
        t1v = (z1*rp1 - rsz1) * invs1;
        t2v = (z2*rp2 - rsz2) * invs2;
        rhs = -(rx + sv[SV_T0] - t1v + t2v + fi * (sv[SV_TA] - sv[SV_TB]));
        gi  = rhs * invD;

        // ---- Pass 5: corrector u1, uf ----
        {
            double a0 = wrs(gi), a1 = wrs(fi * gi);
            if (lane == 0) { wb[0][wid]=a0; wb[1][wid]=a1; }
        }
        __syncthreads();
        if (wid == 0) {
            double u1 = wrs(wb[0][lane]);
            double uf = wrs(wb[1][lane]);
            if (lane == 0) {
                double M11=sv[SV_M11], M22=sv[SV_M22], M12=sv[SV_M12], di=sv[SV_DETINV];
                sv[SV_Y1] = (M22*u1 - M12*uf) * di;
                sv[SV_Y2] = (M11*uf - M12*u1) * di;
            }
        }
        __syncthreads();

        // ---- corrector direction ----
        double dxc  = gi - (sv[SV_Y1] + fi * sv[SV_Y2]) * invD;
        double ds1c = dxc - rp1;
        double ds2c = -rp2 - dxc;
        double dz1c = -(rsz1 + z1 * ds1c) * invs1;
        double dz2c = -(rsz2 + z2 * ds2c) * invs2;
        qs = fmax(fmax(-ds1c, 0.0) * invs1, fmax(-ds2c, 0.0) * invs2);
        qz = fmax(fmax(-dz1c, 0.0) * invz1, fmax(-dz2c, 0.0) * invz2);

        // ---- Pass 6: sum(dx), f.dx, max qs, max qz; final alpha; scalar update ----
        {
            double a0 = wrs(dxc), a1 = wrs(fi * dxc);
            double a2 = wrmax(qs), a3 = wrmax(qz);
            if (lane == 0) { wb[0][wid]=a0; wb[1][wid]=a1; wb[2][wid]=a2; wb[3][wid]=a3; }
        }
        __syncthreads();
        if (wid == 0) {
            double sdx = wrs(wb[0][lane]);
            double fdx = wrs(wb[1][lane]);
            double mqs = wrmax(wb[2][lane]);
            double mqz = wrmax(wb[3][lane]);
            if (lane == 0) {
                double s0 = sv[SV_S0], sA = sv[SV_SA], sB = sv[SV_SB];
                double ds0 = -sv[SV_RP0] - sdx;
                double dsA = -sv[SV_RPA] - fdx;
                double dsB = -sv[SV_RPB] + fdx;
                double dz0 = -(sv[SV_RSZ0] + z0 * ds0) * sv[SV_IS0];
                double dzA = -(sv[SV_RSZA] + zA * dsA) * sv[SV_ISA];
                double dzB = -(sv[SV_RSZB] + zB * dsB) * sv[SV_ISB];
                mqs = fmax(mqs, fmax(-ds0, 0.0) * sv[SV_IS0]);
                mqs = fmax(mqs, fmax(-dsA, 0.0) * sv[SV_ISA]);
                mqs = fmax(mqs, fmax(-dsB, 0.0) * sv[SV_ISB]);
                mqz = fmax(mqz, fmax(-dz0, 0.0) * sv[SV_IZ0]);
                mqz = fmax(mqz, fmax(-dzA, 0.0) * sv[SV_IZA]);
                mqz = fmax(mqz, fmax(-dzB, 0.0) * sv[SV_IZB]);
                double q  = fmax(mqs, mqz);
                double st = (q > 0.0) ? fmin(1.0, 1.0 / q) : 1.0;
                double alpha = 0.99 * st;   // ref: min(1, 0.99*min(steps)); steps<=1
                sv[SV_ALPHA] = alpha;
                sv[SV_S0] = s0 + alpha * ds0;
                sv[SV_SA] = sA + alpha * dsA;
                sv[SV_SB] = sB + alpha * dsB;
                sv[SV_Z0] = z0 + alpha * dz0;
                sv[SV_ZA] = zA + alpha * dzA;
                sv[SV_ZB] = zB + alpha * dzB;
            }
        }
        __syncthreads();

        const double alpha = sv[SV_ALPHA];
        xi += alpha * dxc;
        s1 += alpha * ds1c;  z1 += alpha * dz1c;
        s2 += alpha * ds2c;  z2 += alpha * dz2c;
        // sv[SV_Z0..SV_ZB] written by thread 0 before the sync above -> safe
        // to read at top of next iteration (no writer between here and there).
    }

    out[i] = (float)xi;
}

extern "C" void kernel_launch(void* const* d_in, const int* in_sizes, int n_in,
                              void* d_out, int out_size)
{
    const float* x    = (const float*)d_in[0];
    const int*   male = (const int*)d_in[1];
    float*       out  = (float*)d_out;
    // n is fixed at 1024 for this problem (one thread per coordinate)
    pdip_kernel<<<1, NV>>>(x, male, out);
}

// round 2
// speedup vs baseline: 1.4285x; 1.4285x over previous
#include <cuda_runtime.h>
#include <cuda_bf16.h>

// ============================================================================
// CapLayerLP: 20-iteration predictor-corrector primal-dual interior-point QP
//   min 0.5*eps*||x||^2 + p.x  s.t.  G x <= h,
//   G = [1^T; -I; I; f^T; -f^T]  (n=1024, m=2n+3=2051).
//
// Reduced KKT K = eps*I + diag(z1/s1+z2/s2) + w0*11^T + (wA+wB)*ff^T is
// diagonal + rank-2 -> Woodbury solve with 2x2 capacitance. One block.
//
// Round-2 change: 256 threads x 4 coords/thread (was 1024x1). The 1024-thread
// version forced regs<=64 -> massive fp64 spilling (ncu: regs=64, issue 7.8%).
// Now each thread keeps its 4 coordinate states in registers with 4-way ILP.
// ============================================================================

#define NV    1024
#define T     256
#define VPT   4            // coords per thread
#define NW    (T/32)       // 8 warps
#define MCON  2051.0
#define EPSR  1e-4
#define CCAP  10.0
#define ITERS 20

__device__ __forceinline__ double wrs(double v) {
#pragma unroll
    for (int o = 16; o > 0; o >>= 1) v += __shfl_down_sync(0xffffffffu, v, o);
    return v;
}
__device__ __forceinline__ double wrmax(double v) {
#pragma unroll
    for (int o = 16; o > 0; o >>= 1) v = fmax(v, __shfl_down_sync(0xffffffffu, v, o));
    return v;
}
// stage-2 reduce over NW=8 partials held by lanes 0..7 of warp 0
__device__ __forceinline__ double red8s(double v) {
#pragma unroll
    for (int o = 4; o > 0; o >>= 1) v += __shfl_down_sync(0xffffffffu, v, o);
    return v;
}
__device__ __forceinline__ double red8m(double v) {
#pragma unroll
    for (int o = 4; o > 0; o >>= 1) v = fmax(v, __shfl_down_sync(0xffffffffu, v, o));
    return v;
}

enum {
    SV_Z0 = 0, SV_ZA, SV_ZB,
    SV_T0, SV_TA, SV_TB,
    SV_Y1, SV_Y2,
    SV_AAFF, SV_SMU, SV_ALPHA,
    SV_S0, SV_SA, SV_SB,
    SV_RP0, SV_RPA, SV_RPB,
    SV_IS0, SV_ISA, SV_ISB,
    SV_IZ0, SV_IZA, SV_IZB,
    SV_W0, SV_WA, SV_WB,
    SV_MU,
    SV_M11, SV_M22, SV_M12, SV_DETINV,
    SV_DS0A, SV_DSAA, SV_DSBA, SV_DZ0A, SV_DZAA, SV_DZBA,
    SV_RSZ0, SV_RSZA, SV_RSZB,
    SV_HA, SV_HB,
    SV_CNT
};

__global__ void __launch_bounds__(T, 1)
pdip_kernel(const float* __restrict__ xin, const int* __restrict__ male,
            float* __restrict__ out)
{
    const int i    = threadIdx.x;
    const int lane = i & 31;
    const int wid  = i >> 5;

    __shared__ double wb[5][NW];
    __shared__ double sv[SV_CNT];

    double pi[VPT], fi[VPT];
    double xi[VPT], s1[VPT], z1[VPT], s2[VPT], z2[VPT];
#pragma unroll
    for (int k = 0; k < VPT; ++k) {
        int c = i + k * T;
        pi[k] = -(double)xin[c];
        fi[k] = (double)male[c];
        xi[k] = 0.0; s1[k] = 1.0; z1[k] = 1.0; s2[k] = 1.0; z2[k] = 1.0;
    }

    // ---- init: n_male, h scalars, scalar state ----
    {
        double v = fi[0] + fi[1] + fi[2] + fi[3];
        v = wrs(v);
        if (lane == 0) wb[0][wid] = v;
    }
    __syncthreads();
    if (wid == 0) {
        double v = (lane < NW) ? wb[0][lane] : 0.0;
        v = red8s(v);
        if (lane == 0) {
            double r = CCAP * v / (double)NV;
            sv[SV_HA] = r + 1.0;
            sv[SV_HB] = -r;
            sv[SV_S0] = 1.0; sv[SV_Z0] = 1.0;
            sv[SV_SA] = 1.0; sv[SV_ZA] = 1.0;
            sv[SV_SB] = 1.0; sv[SV_ZB] = 1.0;
        }
    }
    __syncthreads();

    for (int it = 0; it < ITERS; ++it) {
        const double z0 = sv[SV_Z0], zA = sv[SV_ZA], zB = sv[SV_ZB];

        double invs1[VPT], invs2[VPT], invz1[VPT], invz2[VPT], invD[VPT];

        // ---- Pass 1: reciprocals + sums: sum(x), f.x, s.z, sum(1/D), sum(f/D)
        double a0 = 0, a1 = 0, a2 = 0, a3 = 0, a4 = 0;
#pragma unroll
        for (int k = 0; k < VPT; ++k) {
            invs1[k] = 1.0 / s1[k];  invs2[k] = 1.0 / s2[k];
            invz1[k] = 1.0 / z1[k];  invz2[k] = 1.0 / z2[k];
            double w1 = z1[k] * invs1[k], w2 = z2[k] * invs2[k];
            invD[k] = 1.0 / (EPSR + w1 + w2);
            a0 += xi[k];
            a1 += fi[k] * xi[k];
            a2 += s1[k] * z1[k] + s2[k] * z2[k];
            a3 += invD[k];
            a4 += fi[k] * invD[k];
        }
        a0 = wrs(a0); a1 = wrs(a1); a2 = wrs(a2); a3 = wrs(a3); a4 = wrs(a4);
        if (lane == 0) { wb[0][wid]=a0; wb[1][wid]=a1; wb[2][wid]=a2; wb[3][wid]=a3; wb[4][wid]=a4; }
        __syncthreads();
        if (wid == 0) {
            bool ok = lane < NW;
            double sumx = red8s(ok ? wb[0][lane] : 0.0);
            double fx   = red8s(ok ? wb[1][lane] : 0.0);
            double szv  = red8s(ok ? wb[2][lane] : 0.0);
            double SiD  = red8s(ok ? wb[3][lane] : 0.0);
            double SfD  = red8s(ok ? wb[4][lane] : 0.0);
            if (lane == 0) {
                double s0 = sv[SV_S0], sA = sv[SV_SA], sB = sv[SV_SB];
                double rp0 = sumx + s0 - CCAP;
                double rpA =  fx + sA - sv[SV_HA];
                double rpB = -fx + sB - sv[SV_HB];
                double mu  = (szv + s0*z0 + sA*zA + sB*zB) / MCON;
                double is0 = 1.0/s0, isA = 1.0/sA, isB = 1.0/sB;
                double iz0 = 1.0/z0, izA = 1.0/zA, izB = 1.0/zB;
                double w0 = z0*is0, wA = zA*isA, wB = zB*isB;
                double bW = wA + wB;
                sv[SV_RP0]=rp0; sv[SV_RPA]=rpA; sv[SV_RPB]=rpB; sv[SV_MU]=mu;
                sv[SV_IS0]=is0; sv[SV_ISA]=isA; sv[SV_ISB]=isB;
                sv[SV_IZ0]=iz0; sv[SV_IZA]=izA; sv[SV_IZB]=izB;
                sv[SV_W0]=w0;  sv[SV_WA]=wA;  sv[SV_WB]=wB;
                sv[SV_T0] = w0*rp0 - z0;
                sv[SV_TA] = wA*rpA - zA;
                sv[SV_TB] = wB*rpB - zB;
                double M11 = 1.0/w0 + SiD;
                double M22 = 1.0/bW + SfD;
                sv[SV_M11]=M11; sv[SV_M22]=M22; sv[SV_M12]=SfD;
                sv[SV_DETINV] = 1.0 / (M11*M22 - SfD*SfD);
            }
        }
        __syncthreads();

        // ---- predictor rhs, g = D^-1 rhs; Pass 2 sums ----
        double gi[VPT];
        {
            const double T0 = sv[SV_T0], TA = sv[SV_TA], TB = sv[SV_TB];
            double b0 = 0, b1 = 0;
#pragma unroll
            for (int k = 0; k < VPT; ++k) {
                double w1 = z1[k] * invs1[k], w2 = z2[k] * invs2[k];
                double rp1 = s1[k] - xi[k];
                double rp2 = xi[k] + s2[k] - 1.0;
                double rx  = EPSR * xi[k] + pi[k] + (z0 - z1[k] + z2[k] + fi[k] * (zA - zB));
                double t1v = w1 * rp1 - z1[k];
                double t2v = w2 * rp2 - z2[k];
                double rhs = -(rx + T0 - t1v + t2v + fi[k] * (TA - TB));
                gi[k] = rhs * invD[k];
                b0 += gi[k];
                b1 += fi[k] * gi[k];
            }
            b0 = wrs(b0); b1 = wrs(b1);
            if (lane == 0) { wb[0][wid] = b0; wb[1][wid] = b1; }
        }
        __syncthreads();
        if (wid == 0) {
            bool ok = lane < NW;
            double u1 = red8s(ok ? wb[0][lane] : 0.0);
            double uf = red8s(ok ? wb[1][lane] : 0.0);
            if (lane == 0) {
                double M11=sv[SV_M11], M22=sv[SV_M22], M12=sv[SV_M12], di=sv[SV_DETINV];
                sv[SV_Y1] = (M22*u1 - M12*uf) * di;
                sv[SV_Y2] = (M11*uf - M12*u1) * di;
            }
        }
        __syncthreads();

        // ---- affine direction; Pass 3 sums/maxes ----
        double ds1a[VPT], ds2a[VPT], dz1a[VPT], dz2a[VPT];
        {
            const double Y1 = sv[SV_Y1], Y2 = sv[SV_Y2];
            double c0 = 0, c1 = 0, mqs = 0, mqz = 0;
#pragma unroll
            for (int k = 0; k < VPT; ++k) {
                double dxa = gi[k] - (Y1 + fi[k] * Y2) * invD[k];
                double rp1 = s1[k] - xi[k];
                double rp2 = xi[k] + s2[k] - 1.0;
                double w1 = z1[k] * invs1[k], w2 = z2[k] * invs2[k];
                ds1a[k] = dxa - rp1;
                ds2a[k] = -rp2 - dxa;
                dz1a[k] = -z1[k] - w1 * ds1a[k];
                dz2a[k] = -z2[k] - w2 * ds2a[k];
                mqs = fmax(mqs, fmax(fmax(-ds1a[k], 0.0) * invs1[k],
                                     fmax(-ds2a[k], 0.0) * invs2[k]));
                mqz = fmax(mqz, fmax(fmax(-dz1a[k], 0.0) * invz1[k],
                                     fmax(-dz2a[k], 0.0) * invz2[k]));
                c0 += dxa;
                c1 += fi[k] * dxa;
            }
            c0 = wrs(c0); c1 = wrs(c1); mqs = wrmax(mqs); mqz = wrmax(mqz);
            if (lane == 0) { wb[0][wid]=c0; wb[1][wid]=c1; wb[2][wid]=mqs; wb[3][wid]=mqz; }
        }
        __syncthreads();
        if (wid == 0) {
            bool ok = lane < NW;
            double sdx = red8s(ok ? wb[0][lane] : 0.0);
            double fdx = red8s(ok ? wb[1][lane] : 0.0);
            double mqs = red8m(ok ? wb[2][lane] : 0.0);
            double mqz = red8m(ok ? wb[3][lane] : 0.0);
            if (lane == 0) {
                double ds0 = -sv[SV_RP0] - sdx;
                double dsA = -sv[SV_RPA] - fdx;
                double dsB = -sv[SV_RPB] + fdx;
                double dz0 = -z0 - sv[SV_W0] * ds0;
                double dzA = -zA - sv[SV_WA] * dsA;
                double dzB = -zB - sv[SV_WB] * dsB;
                mqs = fmax(mqs, fmax(-ds0, 0.0) * sv[SV_IS0]);
                mqs = fmax(mqs, fmax(-dsA, 0.0) * sv[SV_ISA]);
                mqs = fmax(mqs, fmax(-dsB, 0.0) * sv[SV_ISB]);
                mqz = fmax(mqz, fmax(-dz0, 0.0) * sv[SV_IZ0]);
                mqz = fmax(mqz, fmax(-dzA, 0.0) * sv[SV_IZA]);
                mqz = fmax(mqz, fmax(-dzB, 0.0) * sv[SV_IZB]);
                double q = fmax(mqs, mqz);
                sv[SV_AAFF] = (q > 0.0) ? fmin(1.0, 1.0 / q) : 1.0;
                sv[SV_DS0A]=ds0; sv[SV_DSAA]=dsA; sv[SV_DSBA]=dsB;
                sv[SV_DZ0A]=dz0; sv[SV_DZAA]=dzA; sv[SV_DZBA]=dzB;
            }
        }
        __syncthreads();

        // ---- Pass 4: mu_aff ----
        const double aaff = sv[SV_AAFF];
        {
            double m = 0;
#pragma unroll
            for (int k = 0; k < VPT; ++k)
                m += (s1[k] + aaff*ds1a[k]) * (z1[k] + aaff*dz1a[k])
                   + (s2[k] + aaff*ds2a[k]) * (z2[k] + aaff*dz2a[k]);
            m = wrs(m);
            if (lane == 0) wb[0][wid] = m;
        }
        __syncthreads();
        if (wid == 0) {
            double mv = red8s((lane < NW) ? wb[0][lane] : 0.0);
            if (lane == 0) {
                double s0 = sv[SV_S0], sA = sv[SV_SA], sB = sv[SV_SB];
                double ds0=sv[SV_DS0A], dsA=sv[SV_DSAA], dsB=sv[SV_DSBA];
                double dz0=sv[SV_DZ0A], dzA=sv[SV_DZAA], dzB=sv[SV_DZBA];
                double muaff = (mv
                    + (s0 + aaff*ds0) * (z0 + aaff*dz0)
                    + (sA + aaff*dsA) * (zA + aaff*dzA)
                    + (sB + aaff*dsB) * (zB + aaff*dzB)) / MCON;
                double mu = sv[SV_MU];
                double sg = muaff / mu;
                double smu = sg * sg * sg * mu;
                sv[SV_SMU] = smu;
                double rsz0 = s0*z0 + ds0*dz0 - smu;
                double rszA = sA*zA + dsA*dzA - smu;
                double rszB = sB*zB + dsB*dzB - smu;
                sv[SV_RSZ0]=rsz0; sv[SV_RSZA]=rszA; sv[SV_RSZB]=rszB;
                sv[SV_T0] = (z0*sv[SV_RP0] - rsz0) * sv[SV_IS0];
                sv[SV_TA] = (zA*sv[SV_RPA] - rszA) * sv[SV_ISA];
                sv[SV_TB] = (zB*sv[SV_RPB] - rszB) * sv[SV_ISB];
            }
        }
        __syncthreads();

        // ---- corrector rhs; Pass 5 sums ----
        const double smu = sv[SV_SMU];
        double rsz1[VPT], rsz2[VPT];
        {
            const double T0 = sv[SV_T0], TA = sv[SV_TA], TB = sv[SV_TB];
            double b0 = 0, b1 = 0;
#pragma unroll
            for (int k = 0; k < VPT; ++k) {
                double rp1 = s1[k] - xi[k];
                double rp2 = xi[k] + s2[k] - 1.0;
                double rx  = EPSR * xi[k] + pi[k] + (z0 - z1[k] + z2[k] + fi[k] * (zA - zB));
                rsz1[k] = s1[k]*z1[k] + ds1a[k]*dz1a[k] - smu;
                rsz2[k] = s2[k]*z2[k] + ds2a[k]*dz2a[k] - smu;
                double t1v = (z1[k]*rp1 - rsz1[k]) * invs1[k];
                double t2v = (z2[k]*rp2 - rsz2[k]) * invs2[k];
                double rhs = -(rx + T0 - t1v + t2v + fi[k] * (TA - TB));
                gi[k] = rhs * invD[k];
                b0 += gi[k];
                b1 += fi[k] * gi[k];
            }
            b0 = wrs(b0); b1 = wrs(b1);
            if (lane == 0) { wb[0][wid] = b0; wb[1][wid] = b1; }
        }
        __syncthreads();
        if (wid == 0) {
            bool ok = lane < NW;
            double u1 = red8s(ok ? wb[0][lane] : 0.0);
            double uf = red8s(ok ? wb[1][lane] : 0.0);
            if (lane == 0) {
                double M11=sv[SV_M11], M22=sv[SV_M22], M12=sv[SV_M12], di=sv[SV_DETINV];
                sv[SV_Y1] = (M22*u1 - M12*uf) * di;
                sv[SV_Y2] = (M11*uf - M12*u1) * di;
            }
        }
        __syncthreads();

        // ---- corrector direction; Pass 6 sums/maxes ----
        double dxc[VPT], ds1c[VPT], ds2c[VPT], dz1c[VPT], dz2c[VPT];
        {
            const double Y1 = sv[SV_Y1], Y2 = sv[SV_Y2];
            double c0 = 0, c1 = 0, mqs = 0, mqz = 0;
#pragma unroll
            for (int k = 0; k < VPT; ++k) {
                dxc[k] = gi[k] - (Y1 + fi[k] * Y2) * invD[k];
                double rp1 = s1[k] - xi[k];
                double rp2 = xi[k] + s2[k] - 1.0;
                ds1c[k] = dxc[k] - rp1;
                ds2c[k] = -rp2 - dxc[k];
                dz1c[k] = -(rsz1[k] + z1[k] * ds1c[k]) * invs1[k];
                dz2c[k] = -(rsz2[k] + z2[k] * ds2c[k]) * invs2[k];
                mqs = fmax(mqs, fmax(fmax(-ds1c[k], 0.0) * invs1[k],
                                     fmax(-ds2c[k], 0.0) * invs2[k]));
                mqz = fmax(mqz, fmax(fmax(-dz1c[k], 0.0) * invz1[k],
                                     fmax(-dz2c[k], 0.0) * invz2[k]));
                c0 += dxc[k];
                c1 += fi[k] * dxc[k];
            }
            c0 = wrs(c0); c1 = wrs(c1); mqs = wrmax(mqs); mqz = wrmax(mqz);
            if (lane == 0) { wb[0][wid]=c0; wb[1][wid]=c1; wb[2][wid]=mqs; wb[3][wid]=mqz; }
        }
        __syncthreads();
        if (wid == 0) {
            bool ok = lane < NW;
            double sdx = red8s(ok ? wb[0][lane] : 0.0);
            double fdx = red8s(ok ? wb[1][lane] : 0.0);
            double mqs = red8m(ok ? wb[2][lane] : 0.0);
            double mqz = red8m(ok ? wb[3][lane] : 0.0);
            if (lane == 0) {
                double s0 = sv[SV_S0], sA = sv[SV_SA], sB = sv[SV_SB];
                double ds0 = -sv[SV_RP0] - sdx;
                double dsA = -sv[SV_RPA] - fdx;
                double dsB = -sv[SV_RPB] + fdx;
                double dz0 = -(sv[SV_RSZ0] + z0 * ds0) * sv[SV_IS0];
                double dzA = -(sv[SV_RSZA] + zA * dsA) * sv[SV_ISA];
                double dzB = -(sv[SV_RSZB] + zB * dsB) * sv[SV_ISB];
                mqs = fmax(mqs, fmax(-ds0, 0.0) * sv[SV_IS0]);
                mqs = fmax(mqs, fmax(-dsA, 0.0) * sv[SV_ISA]);
                mqs = fmax(mqs, fmax(-dsB, 0.0) * sv[SV_ISB]);
                mqz = fmax(mqz, fmax(-dz0, 0.0) * sv[SV_IZ0]);
                mqz = fmax(mqz, fmax(-dzA, 0.0) * sv[SV_IZA]);
                mqz = fmax(mqz, fmax(-dzB, 0.0) * sv[SV_IZB]);
                double q  = fmax(mqs, mqz);
                double st = (q > 0.0) ? fmin(1.0, 1.0 / q) : 1.0;
                double alpha = 0.99 * st;
                sv[SV_ALPHA] = alpha;
                sv[SV_S0] = s0 + alpha * ds0;
                sv[SV_SA] = sA + alpha * dsA;
                sv[SV_SB] = sB + alpha * dsB;
                sv[SV_Z0] = z0 + alpha * dz0;
                sv[SV_ZA] = zA + alpha * dzA;
                sv[SV_ZB] = zB + alpha * dzB;
            }
        }
        __syncthreads();

        const double alpha = sv[SV_ALPHA];
#pragma unroll
        for (int k = 0; k < VPT; ++k) {
            xi[k] += alpha * dxc[k];
            s1[k] += alpha * ds1c[k];  z1[k] += alpha * dz1c[k];
            s2[k] += alpha * ds2c[k];  z2[k] += alpha * dz2c[k];
        }
    }

#pragma unroll
    for (int k = 0; k < VPT; ++k)
        out[i + k * T] = (float)xi[k];
}

extern "C" void kernel_launch(void* const* d_in, const int* in_sizes, int n_in,
                              void* d_out, int out_size)
{
    const float* x    = (const float*)d_in[0];
    const int*   male = (const int*)d_in[1];
    float*       out  = (float*)d_out;
    pdip_kernel<<<1, T>>>(x, male, out);
}